// round 17
// baseline (speedup 1.0000x reference)
#include <cuda_runtime.h>
#include <cuda_fp16.h>
#include <cstdint>
#include <cstddef>

#define H_DIM 1024
#define I_DIM 1024
#define C_DIM 64

// ---------------------------------------------------------------------------
// Static scratch (module-load allocated). 256B-aligned for 16B vector access.
// fp16 hi/lo digit planes.
// ---------------------------------------------------------------------------
#define ACT_ELEMS ((size_t)C_DIM * H_DIM * I_DIM)
__device__ __align__(256) __half g_xth[ACT_ELEMS];   // xT hi (later z hi)
__device__ __align__(256) __half g_xtl[ACT_ELEMS];   // xT lo
__device__ __align__(256) __half g_b1h[ACT_ELEMS];   // b1 hi (later pT hi)
__device__ __align__(256) __half g_ph[ACT_ELEMS];    // p hi
__device__ __align__(256) __half g_pl[ACT_ELEMS];    // p lo (stage-4 residual)
__device__ __align__(256) __half g_wph[H_DIM * H_DIM];
__device__ __align__(256) __half g_wpl[H_DIM * H_DIM];
__device__ __align__(256) __half g_plh[I_DIM * I_DIM];
__device__ __align__(256) __half g_pll[I_DIM * I_DIM];
__device__ __align__(256) __half g_wzh[H_DIM * H_DIM];
__device__ __align__(256) __half g_wzl[H_DIM * H_DIM];
__device__ __align__(256) __half g_zlh[I_DIM * I_DIM];
__device__ __align__(256) __half g_zll[I_DIM * I_DIM];

__device__ __forceinline__ float actf(float x) { return fminf(fmaxf(x, -1.0f), 1.0f); }

__device__ __forceinline__ void split_h(float v, __half& hi, __half& lo) {
    hi = __float2half_rn(v);
    lo = __float2half_rn(v - __half2float(hi));
}

// ---------------------------------------------------------------------------
// Prep kernels
// ---------------------------------------------------------------------------
__global__ void prep_wp_kernel(const float* __restrict__ Wp, const float* __restrict__ Wd,
                               __half* __restrict__ Oh, __half* __restrict__ Ol) {
    const int h = blockIdx.x;
    const float dv = Wd[h];
#pragma unroll
    for (int j = 0; j < 4; ++j) {
        const int k = threadIdx.x + j * 256;
        float v = Wp[h * 1024 + k];
        if (k > h) v = 0.0f;
        else if (k == h) v = fminf(fmaxf(v, 0.0f), 1.0f) + dv;
        __half hi, lo; split_h(v, hi, lo);
        Oh[h * 1024 + k] = hi;
        Ol[h * 1024 + k] = lo;
    }
}

__global__ void conv_mat_kernel(const float* __restrict__ W,
                                __half* __restrict__ Oh, __half* __restrict__ Ol) {
    const int i4 = (blockIdx.x * 256 + threadIdx.x) * 4;
    const float4 v = *(const float4*)(W + i4);
    const float vv[4] = {v.x, v.y, v.z, v.w};
    union { uint2 u; __half b[4]; } ph, pl;
#pragma unroll
    for (int e = 0; e < 4; ++e) { split_h(vv[e], ph.b[e], pl.b[e]); }
    *(uint2*)(Oh + i4) = ph.u;
    *(uint2*)(Ol + i4) = pl.u;
}

// XT[c,i,k] = x[c,k,i] * act(pm[k,i]) -> fp16 hi/lo
__global__ void convT_x_kernel(const float* __restrict__ x, const float* __restrict__ pm,
                               __half* __restrict__ Th, __half* __restrict__ Tl) {
    __shared__ float t[32][33];
    const int i0 = blockIdx.x * 32, k0 = blockIdx.y * 32;
    const size_t cOff = (size_t)blockIdx.z << 20;
    const int tx = threadIdx.x, ty = threadIdx.y;
#pragma unroll
    for (int r = 0; r < 4; ++r) {
        const int k = k0 + ty + r * 8;
        const float m = actf(pm[(size_t)k * 1024 + i0 + tx]);
        t[ty + r * 8][tx] = x[cOff + (size_t)k * 1024 + i0 + tx] * m;
    }
    __syncthreads();
#pragma unroll
    for (int r = 0; r < 4; ++r) {
        const int i = i0 + ty + r * 8;
        const float v = t[tx][ty + r * 8];
        __half hi, lo; split_h(v, hi, lo);
        Th[cOff + (size_t)i * 1024 + k0 + tx] = hi;
        Tl[cOff + (size_t)i * 1024 + k0 + tx] = lo;
    }
}

// Single-plane fp16 transpose: T[c,i,h] = P[c,h,i]
__global__ void transP_h_kernel(const __half* __restrict__ P, __half* __restrict__ T) {
    __shared__ __half t[32][34];
    const int i0 = blockIdx.x * 32, h0 = blockIdx.y * 32;
    const size_t cOff = (size_t)blockIdx.z << 20;
    const int tx = threadIdx.x, ty = threadIdx.y;
#pragma unroll
    for (int r = 0; r < 4; ++r) {
        const int h = h0 + ty + r * 8;
        t[ty + r * 8][tx] = P[cOff + (size_t)h * 1024 + i0 + tx];
    }
    __syncthreads();
#pragma unroll
    for (int r = 0; r < 4; ++r) {
        const int i = i0 + ty + r * 8;
        T[cOff + (size_t)i * 1024 + h0 + tx] = t[tx][ty + r * 8];
    }
}

// ---------------------------------------------------------------------------
// mma.sync / ldmatrix / cp.async helpers (base ISA, valid on target sm_103)
// ---------------------------------------------------------------------------
__device__ __forceinline__ void mma16816(float* d, const uint32_t* a, const uint32_t* b) {
    asm volatile(
        "mma.sync.aligned.m16n8k16.row.col.f32.f16.f16.f32 "
        "{%0,%1,%2,%3}, {%4,%5,%6,%7}, {%8,%9}, {%0,%1,%2,%3};"
        : "+f"(d[0]), "+f"(d[1]), "+f"(d[2]), "+f"(d[3])
        : "r"(a[0]), "r"(a[1]), "r"(a[2]), "r"(a[3]), "r"(b[0]), "r"(b[1]));
}
// fp16-accumulator variant: D/C are 4 halves in 2 b32 regs. Used only for the
// low-order correction passes (tiny magnitudes -> fp16 accum error negligible).
__device__ __forceinline__ void mma16816_h(uint32_t* d, const uint32_t* a, const uint32_t* b) {
    asm volatile(
        "mma.sync.aligned.m16n8k16.row.col.f16.f16.f16.f16 "
        "{%0,%1}, {%2,%3,%4,%5}, {%6,%7}, {%0,%1};"
        : "+r"(d[0]), "+r"(d[1])
        : "r"(a[0]), "r"(a[1]), "r"(a[2]), "r"(a[3]), "r"(b[0]), "r"(b[1]));
}
__device__ __forceinline__ void ldm_x4(uint32_t* r, uint32_t addr) {
    asm volatile("ldmatrix.sync.aligned.m8n8.x4.shared.b16 {%0,%1,%2,%3}, [%4];"
                 : "=r"(r[0]), "=r"(r[1]), "=r"(r[2]), "=r"(r[3]) : "r"(addr));
}
__device__ __forceinline__ void cp16(uint32_t dst, const void* src) {
    asm volatile("cp.async.cg.shared.global [%0], [%1], 16;" :: "r"(dst), "l"(src) : "memory");
}
__device__ __forceinline__ uint32_t smem_u32(const void* p) {
    uint32_t a;
    asm("{ .reg .u64 t; cvta.to.shared.u64 t, %1; cvt.u32.u64 %0, t; }" : "=r"(a) : "l"(p));
    return a;
}

// ---------------------------------------------------------------------------
// fp16 split GEMM: D[m,n] = sum_k A[m,k]*B[n,k] (both K-contiguous).
// hi*hi pass -> fp32 accumulators; correction passes (Ah*Bl / Al*Bh) -> fp16
// accumulators (testing the 2x f16-accum rate hypothesis), combined in epilogue.
// Tile 128x128, BK=32, 8 warps (64x32 each), 3-stage cp.async pipeline,
// 80B-pitch smem (conflict-free ldmatrix), 16 independent MMAs per pass.
// APC/BPC: per-channel operand. TRI: triangular k-skip (stage 1).
// EPI: 0 = act -> hi(+lo if OLO); 1 = +bias; 2 = act(+bias)+residual -> f32.
// ---------------------------------------------------------------------------
#define TILE_B 10240        // 128 rows * 80 bytes
#define BUF_B  (4 * TILE_B) // slots: Ah, Al, Bh, Bl
#define NSTAGE 3

template <int APC, int BPC, int TRI, int EPI, int ALO, int BLO, int OLO>
__global__ __launch_bounds__(256, 1)
void gemm_mma(const __half* __restrict__ Ah, const __half* __restrict__ Al,
              const __half* __restrict__ Bh, const __half* __restrict__ Bl,
              const float* __restrict__ bias,
              const __half* __restrict__ Rh, const __half* __restrict__ Rl,
              __half* __restrict__ Oh, __half* __restrict__ Ol,
              float* __restrict__ Of)
{
    extern __shared__ char smem[];
    const uint32_t sb = smem_u32(smem);
    const int tid = threadIdx.x;
    const int wid = tid >> 5;
    const int lane = tid & 31;
    const int gID = lane >> 2;
    const int tg  = lane & 3;
    const int warp_m = wid & 1;
    const int warp_n = wid >> 1;
    const int n0 = blockIdx.x * 128;
    const int m0 = blockIdx.y * 128;
    const size_t cOff = (size_t)blockIdx.z << 20;

    const int nch = TRI ? (blockIdx.y + 1) * 4 : 32;   // BK=32 chunks

    const __half* pAh = Ah + (APC ? cOff : 0) + (size_t)m0 * 1024;
    const __half* pAl = ALO ? (Al + (APC ? cOff : 0) + (size_t)m0 * 1024) : nullptr;
    const __half* pBh = Bh + (BPC ? cOff : 0) + (size_t)n0 * 1024;
    const __half* pBl = BLO ? (Bl + (BPC ? cOff : 0) + (size_t)n0 * 1024) : nullptr;

    auto issue = [&](int kc, int st) {
        const uint32_t base = sb + st * BUF_B;
#pragma unroll
        for (int i = 0; i < 2; ++i) {
            const int u = tid + i * 256;
            const int row = u >> 2;
            const int c16 = u & 3;
            const uint32_t doff = row * 80 + c16 * 16;
            const size_t so = (size_t)row * 1024 + kc * 32 + c16 * 8;
            cp16(base + doff, pAh + so);
            if (ALO) cp16(base + TILE_B + doff, pAl + so);
            cp16(base + 2 * TILE_B + doff, pBh + so);
            if (BLO) cp16(base + 3 * TILE_B + doff, pBl + so);
        }
        asm volatile("cp.async.commit_group;" ::: "memory");
    };

    const uint32_t a_off = (uint32_t)((warp_m * 64 + (lane & 7) + ((lane >> 3) & 1) * 8) * 80
                                      + (lane >> 4) * 16);
    const uint32_t b_off = (uint32_t)((warp_n * 32 + (lane & 7) + ((lane >> 4) & 1) * 8) * 80
                                      + ((lane >> 3) & 1) * 16);

    float acc[4][4][4];
    uint32_t hacc[4][4][2];   // fp16 correction accumulators (2 halves per reg)
#pragma unroll
    for (int mt = 0; mt < 4; ++mt)
#pragma unroll
        for (int nt = 0; nt < 4; ++nt) {
#pragma unroll
            for (int r = 0; r < 4; ++r) acc[mt][nt][r] = 0.0f;
            hacc[mt][nt][0] = 0u; hacc[mt][nt][1] = 0u;
        }

    issue(0, 0);
    issue(1, 1);

    for (int kc = 0; kc < nch; ++kc) {
        if (kc + 1 < nch) {
            asm volatile("cp.async.wait_group 1;" ::: "memory");
        } else {
            asm volatile("cp.async.wait_group 0;" ::: "memory");
        }
        __syncthreads();
        if (kc + 2 < nch) issue(kc + 2, (kc + 2) % NSTAGE);

        const uint32_t bAh = sb + (kc % NSTAGE) * BUF_B;
        const uint32_t bAl = bAh + TILE_B;
        const uint32_t bBh = bAh + 2 * TILE_B;
        const uint32_t bBl = bAh + 3 * TILE_B;

#pragma unroll
        for (int ks = 0; ks < 2; ++ks) {
            const uint32_t ko = ks * 32;
            uint32_t ah[4][4], al[4][4], bhf[4][2], blf[4][2];
#pragma unroll
            for (int mt = 0; mt < 4; ++mt) {
                ldm_x4(ah[mt], bAh + a_off + mt * 1280 + ko);
                if (ALO) ldm_x4(al[mt], bAl + a_off + mt * 1280 + ko);
            }
#pragma unroll
            for (int np = 0; np < 2; ++np) {
                uint32_t t0[4];
                ldm_x4(t0, bBh + b_off + np * 1280 + ko);
                bhf[2 * np][0] = t0[0]; bhf[2 * np][1] = t0[1];
                bhf[2 * np + 1][0] = t0[2]; bhf[2 * np + 1][1] = t0[3];
                if (BLO) {
                    uint32_t t1[4];
                    ldm_x4(t1, bBl + b_off + np * 1280 + ko);
                    blf[2 * np][0] = t1[0]; blf[2 * np][1] = t1[1];
                    blf[2 * np + 1][0] = t1[2]; blf[2 * np + 1][1] = t1[3];
                }
            }
            // Pass 1: Ah*Bh -> fp32 accum (16 independent HMMAs)
#pragma unroll
            for (int mt = 0; mt < 4; ++mt)
#pragma unroll
                for (int nt = 0; nt < 4; ++nt)
                    mma16816(acc[mt][nt], ah[mt], bhf[nt]);
            // Pass 2: Ah*Bl -> fp16 accum
            if (BLO) {
#pragma unroll
                for (int mt = 0; mt < 4; ++mt)
#pragma unroll
                    for (int nt = 0; nt < 4; ++nt)
                        mma16816_h(hacc[mt][nt], ah[mt], blf[nt]);
            }
            // Pass 3: Al*Bh -> fp16 accum
            if (ALO) {
#pragma unroll
                for (int mt = 0; mt < 4; ++mt)
#pragma unroll
                    for (int nt = 0; nt < 4; ++nt)
                        mma16816_h(hacc[mt][nt], al[mt], bhf[nt]);
            }
        }
    }
    __syncthreads();

    // Fold fp16 correction accumulators into fp32 accumulators.
    if (ALO || BLO) {
#pragma unroll
        for (int mt = 0; mt < 4; ++mt)
#pragma unroll
            for (int nt = 0; nt < 4; ++nt) {
                const __half2 h01 = *reinterpret_cast<const __half2*>(&hacc[mt][nt][0]);
                const __half2 h23 = *reinterpret_cast<const __half2*>(&hacc[mt][nt][1]);
                const float2 f01 = __half22float2(h01);
                const float2 f23 = __half22float2(h23);
                acc[mt][nt][0] += f01.x; acc[mt][nt][1] += f01.y;
                acc[mt][nt][2] += f23.x; acc[mt][nt][3] += f23.y;
            }
    }

    // --- Epilogue: stage fp32 tile in smem (pitch 129), then coalesced stores ---
    float* F = (float*)smem;
#pragma unroll
    for (int mt = 0; mt < 4; ++mt)
#pragma unroll
        for (int nt = 0; nt < 4; ++nt)
#pragma unroll
            for (int r = 0; r < 4; ++r) {
                const int rr = warp_m * 64 + mt * 16 + gID + (r >= 2 ? 8 : 0);
                const int cc = warp_n * 32 + nt * 8 + 2 * tg + (r & 1);
                F[rr * 129 + cc] = acc[mt][nt][r];
            }
    __syncthreads();

    {
        const int r  = tid >> 1;
        const int hf = tid & 1;
        const float* Frow = F + r * 129 + hf * 64;
        const size_t ob = cOff + (size_t)(m0 + r) * 1024 + n0 + hf * 64;
        const int jb = n0 + hf * 64;

        float bj[64];
        if (EPI >= 1) {
#pragma unroll
            for (int e4 = 0; e4 < 16; ++e4) {
                const float4 bv = *(const float4*)(bias + jb + e4 * 4);
                bj[e4 * 4 + 0] = bv.x; bj[e4 * 4 + 1] = bv.y;
                bj[e4 * 4 + 2] = bv.z; bj[e4 * 4 + 3] = bv.w;
            }
        }

#pragma unroll
        for (int g = 0; g < 8; ++g) {
            float v[8];
#pragma unroll
            for (int e = 0; e < 8; ++e) {
                float t = Frow[g * 8 + e];
                if (EPI >= 1) t += bj[g * 8 + e];
                v[e] = actf(t);
            }
            if (EPI == 2) {
                union { uint4 u; __half b[8]; } rh, rl;
                rh.u = *(const uint4*)(Rh + ob + g * 8);
                rl.u = *(const uint4*)(Rl + ob + g * 8);
                float4 o0, o1;
                o0.x = v[0] + __half2float(rh.b[0]) + __half2float(rl.b[0]);
                o0.y = v[1] + __half2float(rh.b[1]) + __half2float(rl.b[1]);
                o0.z = v[2] + __half2float(rh.b[2]) + __half2float(rl.b[2]);
                o0.w = v[3] + __half2float(rh.b[3]) + __half2float(rl.b[3]);
                o1.x = v[4] + __half2float(rh.b[4]) + __half2float(rl.b[4]);
                o1.y = v[5] + __half2float(rh.b[5]) + __half2float(rl.b[5]);
                o1.z = v[6] + __half2float(rh.b[6]) + __half2float(rl.b[6]);
                o1.w = v[7] + __half2float(rh.b[7]) + __half2float(rl.b[7]);
                *(float4*)(Of + ob + g * 8)     = o0;
                *(float4*)(Of + ob + g * 8 + 4) = o1;
            } else {
                union { uint4 u; __half b[8]; } oh_, ol_;
#pragma unroll
                for (int e = 0; e < 8; ++e) split_h(v[e], oh_.b[e], ol_.b[e]);
                *(uint4*)(Oh + ob + g * 8) = oh_.u;
                if (OLO) *(uint4*)(Ol + ob + g * 8) = ol_.u;
            }
        }
    }
}

// ---------------------------------------------------------------------------
// Host launcher
// ---------------------------------------------------------------------------
extern "C" void kernel_launch(void* const* d_in, const int* in_sizes, int n_in,
                              void* d_out, int out_size)
{
    (void)in_sizes; (void)n_in; (void)out_size;
    const float* x       = (const float*)d_in[0];
    const float* p_mask  = (const float*)d_in[1];
    const float* Wp      = (const float*)d_in[2];
    const float* Wp_diag = (const float*)d_in[3];
    const float* Wzp     = (const float*)d_in[4];
    const float* p_lin_w = (const float*)d_in[5];
    const float* p_lin_b = (const float*)d_in[6];
    const float* z_lin_w = (const float*)d_in[7];
    const float* z_lin_b = (const float*)d_in[8];
    float* out = (float*)d_out;

    __half *xth, *xtl, *b1h, *ph, *pl;
    __half *wph, *wpl, *plh, *pll, *wzh, *wzl, *zlh, *zll;
    cudaGetSymbolAddress((void**)&xth, g_xth); cudaGetSymbolAddress((void**)&xtl, g_xtl);
    cudaGetSymbolAddress((void**)&b1h, g_b1h);
    cudaGetSymbolAddress((void**)&ph,  g_ph);  cudaGetSymbolAddress((void**)&pl,  g_pl);
    cudaGetSymbolAddress((void**)&wph, g_wph); cudaGetSymbolAddress((void**)&wpl, g_wpl);
    cudaGetSymbolAddress((void**)&plh, g_plh); cudaGetSymbolAddress((void**)&pll, g_pll);
    cudaGetSymbolAddress((void**)&wzh, g_wzh); cudaGetSymbolAddress((void**)&wzl, g_wzl);
    cudaGetSymbolAddress((void**)&zlh, g_zlh); cudaGetSymbolAddress((void**)&zll, g_zll);

    const int SMEM = NSTAGE * BUF_B;  // 122880 (>= epilogue staging 128*129*4)
    cudaFuncSetAttribute(gemm_mma<0,1,1,0,1,1,0>, cudaFuncAttributeMaxDynamicSharedMemorySize, SMEM);
    cudaFuncSetAttribute(gemm_mma<1,0,0,1,0,1,1>, cudaFuncAttributeMaxDynamicSharedMemorySize, SMEM);
    cudaFuncSetAttribute(gemm_mma<0,1,0,0,1,0,0>, cudaFuncAttributeMaxDynamicSharedMemorySize, SMEM);
    cudaFuncSetAttribute(gemm_mma<1,0,0,2,0,1,0>, cudaFuncAttributeMaxDynamicSharedMemorySize, SMEM);

    // Prep: fp16 hi/lo weight splits + masked/transposed x
    prep_wp_kernel<<<H_DIM, 256>>>(Wp, Wp_diag, wph, wpl);
    conv_mat_kernel<<<1024, 256>>>(p_lin_w, plh, pll);
    conv_mat_kernel<<<1024, 256>>>(Wzp, wzh, wzl);
    conv_mat_kernel<<<1024, 256>>>(z_lin_w, zlh, zll);
    convT_x_kernel<<<dim3(32, 32, C_DIM), dim3(32, 8)>>>(x, p_mask, xth, xtl);

    const dim3 gg(8, 8, C_DIM);
    // Stage 1 (hi*hi fp32 + 2 corrections fp16): b1 = act(Wp_eff @ pset); hi only
    gemm_mma<0,1,1,0,1,1,0><<<gg, 256, SMEM>>>(wph, wpl, xth, xtl,
                                               nullptr, nullptr, nullptr,
                                               b1h, nullptr, nullptr);
    // Stage 2 (hi*hi + 1 corr): p = act(b1 @ p_lin_w^T + b); store hi+lo
    gemm_mma<1,0,0,1,0,1,1><<<gg, 256, SMEM>>>(b1h, nullptr, plh, pll,
                                               p_lin_b, nullptr, nullptr,
                                               ph, pl, nullptr);
    // Transpose p hi-plane for stage 3 (into b1h, now dead)
    transP_h_kernel<<<dim3(32, 32, C_DIM), dim3(32, 8)>>>(ph, b1h);
    // Stage 3 (hi*hi + 1 corr): z = act(Wzp @ p); store hi only -> xth (dead)
    gemm_mma<0,1,0,0,1,0,0><<<gg, 256, SMEM>>>(wzh, wzl, b1h, nullptr,
                                               nullptr, nullptr, nullptr,
                                               xth, nullptr, nullptr);
    // Stage 4 (hi*hi + 1 corr): out = p + act(z @ z_lin_w^T + b)
    gemm_mma<1,0,0,2,0,1,0><<<gg, 256, SMEM>>>(xth, nullptr, zlh, zll,
                                               z_lin_b, ph, pl,
                                               nullptr, nullptr, out);
}